// round 2
// baseline (speedup 1.0000x reference)
#include <cuda_runtime.h>
#include <math.h>

#define NS        100
#define NPIX      (NS * NS)
#define PARTS     8
#define MAXPARTS  16
#define BLOCK     128
#define INF_F     1000000000.0f
#define MU_F      1e-8f
#define SAFE_THR  0.05f

__global__ __launch_bounds__(BLOCK)
void physical_circle_kernel(const float* __restrict__ seg_maps,      // (B,100,100)
                            const float* __restrict__ seg_map_paras, // (B,6)
                            const float* __restrict__ trajectories,  // (B,8,2)
                            const float* __restrict__ current_pos,   // (B,1,2)
                            float* __restrict__ out)                 // (B,16,3)
{
    const int b    = blockIdx.x;
    const int tid  = threadIdx.x;
    const int lane = tid & 31;
    const int wid  = tid >> 5;

    __shared__ float sp[8];      // invW0, invW1, offI, offJ, r2, ml, swap
    __shared__ int   sbb[4];     // il, ih, jl, jh
    __shared__ int   smin[PARTS];

    if (tid < PARTS) smin[tid] = __float_as_int(INF_F);
    if (tid == 0) {
        const float* pr = seg_map_paras + b * 6;
        float W0 = pr[0], W1 = pr[1], b0 = pr[2], b1 = pr[3], order0 = pr[4];
        bool swap = (order0 == 1.0f);

        const float* tr = trajectories + b * 16;
        float mvx = tr[14] - tr[0];
        float mvy = tr[15] - tr[1];
        float ml  = sqrtf(mvx * mvx + mvy * mvy);
        float r   = 2.0f * ml;

        float cx = current_pos[b * 2 + 0];
        float cy = current_pos[b * 2 + 1];

        float invW0 = 1.0f / W0;
        float invW1 = 1.0f / W1;
        // dirI = fmaf(i, invW0, offI); dirJ = fmaf(j, invW1, offJ)
        float offI = -b0 * invW0 - (swap ? cy : cx);
        float offJ = -b1 * invW1 - (swap ? cx : cy);

        sp[0] = invW0; sp[1] = invW1; sp[2] = offI; sp[3] = offJ;
        sp[4] = r * r; sp[5] = ml;    sp[6] = swap ? 1.0f : 0.0f;

        // conservative bbox of |dirI|<=r, |dirJ|<=r in pixel space (+/-1 margin)
        float W0f = W0, W1f = W1;   // positive (in [1,2])
        int il = (int)floorf((-r - offI) * W0f) - 1;
        int ih = (int)ceilf (( r - offI) * W0f) + 1;
        int jl = (int)floorf((-r - offJ) * W1f) - 1;
        int jh = (int)ceilf (( r - offJ) * W1f) + 1;
        il = max(il, 0);  ih = min(ih, NS - 1);
        jl = max(jl, 0);  jh = min(jh, NS - 1);
        sbb[0] = il; sbb[1] = ih; sbb[2] = jl; sbb[3] = jh;
    }
    __syncthreads();

    const float invW0 = sp[0], invW1 = sp[1], offI = sp[2], offJ = sp[3];
    const float r2 = sp[4], ml = sp[5];
    const bool  swp = (sp[6] != 0.0f);
    const int il = sbb[0], ih = sbb[1], jl = sbb[2], jh = sbb[3];

    float lmin[PARTS];
#pragma unroll
    for (int p = 0; p < PARTS; ++p) lmin[p] = INF_F;

    const float* mp = seg_maps + (size_t)b * NPIX;

    // warp per row (strided), lane per column (coalesced contiguous segment)
    for (int i = il + wid; i <= ih; i += (BLOCK / 32)) {
        float dirI  = fmaf((float)i, invW0, offI);
        float dirI2 = dirI * dirI;
        const float* rowp = mp + i * NS;
        for (int j = jl + lane; j <= jh; j += 32) {
            float m    = __ldg(rowp + j);
            float dirJ = fmaf((float)j, invW1, offJ);
            float dd   = fmaf(dirJ, dirJ, dirI2);
            if (m > SAFE_THR && dd <= r2) {
                float dist = sqrtf(dd);
                float eq   = (dist + MU_F) / (m + MU_F);
                float s = swp ? dirJ : dirI;   // angle = atan2(s, c)
                float c = swp ? dirI : dirJ;
                int bin;
                if (s >= 0.0f) {
                    if (c >= 0.0f) bin = (s <= c)  ? 0 : 1;
                    else           bin = (s >= -c) ? 2 : 3;
                } else {
                    if (c <= 0.0f) bin = (-s <= -c) ? 4 : 5;
                    else           bin = (-s >= c)  ? 6 : 7;
                }
#pragma unroll
                for (int p = 0; p < PARTS; ++p)
                    lmin[p] = (bin == p) ? fminf(lmin[p], eq) : lmin[p];
            }
        }
    }

#pragma unroll
    for (int p = 0; p < PARTS; ++p) {
        float v = lmin[p];
#pragma unroll
        for (int o = 16; o > 0; o >>= 1)
            v = fminf(v, __shfl_xor_sync(0xffffffffu, v, o));
        if (lane == 0)
            atomicMin(&smin[p], __float_as_int(v));  // values >= 0: int order == float order
    }
    __syncthreads();

    if (tid < MAXPARTS) {
        float fv = 0.0f, fd = 0.0f, fr = 0.0f;
        if (tid < PARTS) {
            float md = fminf(__int_as_float(smin[tid]), INF_F);
            if (md < INF_F) {
                fv = ml;
                fd = md;
                fr = (float)(6.283185307179586 * ((double)tid + 0.5) / 8.0);
            }
        }
        float* o = out + (size_t)b * (MAXPARTS * 3) + tid * 3;
        o[0] = fv; o[1] = fd; o[2] = fr;
    }
}

extern "C" void kernel_launch(void* const* d_in, const int* in_sizes, int n_in,
                              void* d_out, int out_size)
{
    const float* seg_maps      = (const float*)d_in[0];
    const float* seg_map_paras = (const float*)d_in[1];
    const float* trajectories  = (const float*)d_in[2];
    const float* current_pos   = (const float*)d_in[3];
    float* out = (float*)d_out;

    int B = in_sizes[0] / NPIX;   // 1024
    physical_circle_kernel<<<B, BLOCK>>>(seg_maps, seg_map_paras, trajectories,
                                         current_pos, out);
}

// round 3
// speedup vs baseline: 1.4570x; 1.4570x over previous
#include <cuda_runtime.h>
#include <math.h>

#define NS        100
#define NPIX      (NS * NS)
#define PARTS     8
#define MAXPARTS  16
#define BLOCK     256
#define UNROLL    4
#define INF_F     1000000000.0f
#define MU_F      1e-8f
#define SAFE_THR  0.05f

__global__ __launch_bounds__(BLOCK)
void physical_circle_kernel(const float* __restrict__ seg_maps,      // (B,100,100)
                            const float* __restrict__ seg_map_paras, // (B,6)
                            const float* __restrict__ trajectories,  // (B,8,2)
                            const float* __restrict__ current_pos,   // (B,1,2)
                            float* __restrict__ out)                 // (B,16,3)
{
    const int b    = blockIdx.x;
    const int tid  = threadIdx.x;
    const int lane = tid & 31;

    __shared__ float sp[8];      // invW0, invW1, offI, offJ, r2, ml, swap
    __shared__ int   sbb[3];     // il, jl, tot (flattened count), Wd
    __shared__ int   swd[1];
    __shared__ int   smin[PARTS];

    if (tid < PARTS) smin[tid] = __float_as_int(INF_F);
    if (tid == 0) {
        const float* pr = seg_map_paras + b * 6;
        float W0 = pr[0], W1 = pr[1], b0 = pr[2], b1 = pr[3], order0 = pr[4];
        bool swap = (order0 == 1.0f);

        const float* tr = trajectories + b * 16;
        float mvx = tr[14] - tr[0];
        float mvy = tr[15] - tr[1];
        float ml  = sqrtf(mvx * mvx + mvy * mvy);
        float r   = 2.0f * ml;

        float cx = current_pos[b * 2 + 0];
        float cy = current_pos[b * 2 + 1];

        float invW0 = 1.0f / W0;
        float invW1 = 1.0f / W1;
        // dirI = fmaf(i, invW0, offI); dirJ = fmaf(j, invW1, offJ)
        float offI = -b0 * invW0 - (swap ? cy : cx);
        float offJ = -b1 * invW1 - (swap ? cx : cy);

        sp[0] = invW0; sp[1] = invW1; sp[2] = offI; sp[3] = offJ;
        sp[4] = r * r; sp[5] = ml;    sp[6] = swap ? 1.0f : 0.0f;

        // conservative pixel-space bbox of the valid disk (+/-1 px margin)
        int il = (int)floorf((-r - offI) * W0) - 1;
        int ih = (int)ceilf (( r - offI) * W0) + 1;
        int jl = (int)floorf((-r - offJ) * W1) - 1;
        int jh = (int)ceilf (( r - offJ) * W1) + 1;
        il = max(il, 0);  ih = min(ih, NS - 1);
        jl = max(jl, 0);  jh = min(jh, NS - 1);
        int Wd = jh - jl + 1;
        int Hd = ih - il + 1;
        int tot = (Wd > 0 && Hd > 0) ? Wd * Hd : 0;
        sbb[0] = il; sbb[1] = jl; sbb[2] = tot;
        swd[0] = (Wd > 0) ? Wd : 1;
    }
    __syncthreads();

    const float invW0 = sp[0], invW1 = sp[1], offI = sp[2], offJ = sp[3];
    const float r2 = sp[4], ml = sp[5];
    const bool  swp = (sp[6] != 0.0f);
    const int il = sbb[0], jl = sbb[1], tot = sbb[2];
    const unsigned Wd = (unsigned)swd[0];

    float lmin[PARTS];
#pragma unroll
    for (int p = 0; p < PARTS; ++p) lmin[p] = INF_F;

    const float* mp = seg_maps + (size_t)b * NPIX;

    // flattened bbox, 4-way batched loads for MLP
    for (int base = 0; base < tot; base += BLOCK * UNROLL) {
        float mv[UNROLL];
        float dI[UNROLL], dJ[UNROLL];
        bool  act[UNROLL];
#pragma unroll
        for (int k = 0; k < UNROLL; ++k) {
            int idx = base + k * BLOCK + tid;
            act[k] = (idx < tot);
            unsigned ui = act[k] ? (unsigned)idx : 0u;
            unsigned qi = ui / Wd;
            unsigned qj = ui - qi * Wd;
            int i = il + (int)qi;
            int j = jl + (int)qj;
            dI[k] = fmaf((float)i, invW0, offI);
            dJ[k] = fmaf((float)j, invW1, offJ);
            mv[k] = act[k] ? __ldg(mp + i * NS + j) : 0.0f;
        }
#pragma unroll
        for (int k = 0; k < UNROLL; ++k) {
            float dirI = dI[k], dirJ = dJ[k], m = mv[k];
            float dirI2 = dirI * dirI;
            float dd    = fmaf(dirJ, dirJ, dirI2);
            if (act[k] && m > SAFE_THR && dd <= r2) {
                float dist = sqrtf(dd);
                float eq   = (dist + MU_F) / (m + MU_F);
                float s = swp ? dirJ : dirI;   // angle = atan2(s, c)
                float c = swp ? dirI : dirJ;
                int bin;
                if (s >= 0.0f) {
                    if (c >= 0.0f) bin = (s <= c)  ? 0 : 1;
                    else           bin = (s >= -c) ? 2 : 3;
                } else {
                    if (c <= 0.0f) bin = (-s <= -c) ? 4 : 5;
                    else           bin = (-s >= c)  ? 6 : 7;
                }
#pragma unroll
                for (int p = 0; p < PARTS; ++p)
                    lmin[p] = (bin == p) ? fminf(lmin[p], eq) : lmin[p];
            }
        }
    }

#pragma unroll
    for (int p = 0; p < PARTS; ++p) {
        float v = lmin[p];
#pragma unroll
        for (int o = 16; o > 0; o >>= 1)
            v = fminf(v, __shfl_xor_sync(0xffffffffu, v, o));
        if (lane == 0)
            atomicMin(&smin[p], __float_as_int(v));  // values >= 0: int order == float order
    }
    __syncthreads();

    if (tid < MAXPARTS) {
        float fv = 0.0f, fd = 0.0f, fr = 0.0f;
        if (tid < PARTS) {
            float md = fminf(__int_as_float(smin[tid]), INF_F);
            if (md < INF_F) {
                fv = ml;
                fd = md;
                fr = (float)(6.283185307179586 * ((double)tid + 0.5) / 8.0);
            }
        }
        float* o = out + (size_t)b * (MAXPARTS * 3) + tid * 3;
        o[0] = fv; o[1] = fd; o[2] = fr;
    }
}

extern "C" void kernel_launch(void* const* d_in, const int* in_sizes, int n_in,
                              void* d_out, int out_size)
{
    const float* seg_maps      = (const float*)d_in[0];
    const float* seg_map_paras = (const float*)d_in[1];
    const float* trajectories  = (const float*)d_in[2];
    const float* current_pos   = (const float*)d_in[3];
    float* out = (float*)d_out;

    int B = in_sizes[0] / NPIX;   // 1024
    physical_circle_kernel<<<B, BLOCK>>>(seg_maps, seg_map_paras, trajectories,
                                         current_pos, out);
}